// round 12
// baseline (speedup 1.0000x reference)
#include <cuda_runtime.h>

// 3x3 median blur, zero padding, fp32 NCHW (8,3,512,512).
// 4 output rows x 4 cols per thread (16 px, 16 alu ops/px) with R7-style
// liveness phasing: windows A..D computed in sequence, pair-sorts and row
// registers die at last use, next row's load issued as stores free regs.
// Target <=51 regs @ __launch_bounds__(128,10) -> 62.5% occupancy
// (vs 64 regs / 39% for the unphased 4x4).

__device__ __forceinline__ float med3(float a, float b, float c) {
    return fmaxf(fminf(a, b), fminf(fmaxf(a, b), c));
}

// Insert row r into sorted pairs (mn, mx) -> sorted triples.
__device__ __forceinline__ void triples(const float r[6], const float mn[6],
                                        const float mx[6],
                                        float lo[6], float mi[6], float hi[6]) {
    #pragma unroll
    for (int j = 0; j < 6; ++j) {
        const float u = fmaxf(r[j], mn[j]);
        lo[j] = fminf(r[j], mn[j]);
        mi[j] = fminf(u, mx[j]);
        hi[j] = fmaxf(u, mx[j]);
    }
}

// Merge 6 sorted column triples into 4 medians; shared pairs across pixels.
__device__ __forceinline__ void merge_row(const float lo[6], const float mi[6],
                                          const float hi[6], float* dst) {
    const float m12 = fmaxf(lo[1], lo[2]);
    const float m34 = fmaxf(lo[3], lo[4]);
    const float A0 = fmaxf(lo[0], m12);
    const float A1 = fmaxf(m12, lo[3]);
    const float A2 = fmaxf(lo[2], m34);
    const float A3 = fmaxf(m34, lo[5]);
    const float n12 = fminf(hi[1], hi[2]);
    const float n34 = fminf(hi[3], hi[4]);
    const float C0 = fminf(hi[0], n12);
    const float C1 = fminf(n12, hi[3]);
    const float C2 = fminf(hi[2], n34);
    const float C3 = fminf(n34, hi[5]);
    const float p12 = fminf(mi[1], mi[2]), q12 = fmaxf(mi[1], mi[2]);
    const float p34 = fminf(mi[3], mi[4]), q34 = fmaxf(mi[3], mi[4]);
    const float B0 = fmaxf(p12, fminf(mi[0], q12));
    const float B1 = fmaxf(p12, fminf(mi[3], q12));
    const float B2 = fmaxf(p34, fminf(mi[2], q34));
    const float B3 = fmaxf(p34, fminf(mi[5], q34));
    float4 o;
    o.x = med3(A0, B0, C0);
    o.y = med3(A1, B1, C1);
    o.z = med3(A2, B2, C2);
    o.w = med3(A3, B3, C3);
    *reinterpret_cast<float4*>(dst) = o;
}

template <bool CHECK>
__device__ __forceinline__ void load_row(float dst[6], const float* __restrict__ p,
                                         int yy, int x0, bool lx, bool rx) {
    if (CHECK && (unsigned)yy >= 512u) {
        #pragma unroll
        for (int j = 0; j < 6; ++j) dst[j] = 0.0f;
    } else {
        const float* __restrict__ row = p + yy * 512;
        const float4 a = *reinterpret_cast<const float4*>(row + x0);
        dst[1] = a.x; dst[2] = a.y; dst[3] = a.z; dst[4] = a.w;
        dst[0] = lx ? row[x0 - 1] : 0.0f;
        dst[5] = rx ? row[x0 + 4] : 0.0f;
    }
}

template <bool CHECK>
__device__ __forceinline__ void tile4x4(const float* __restrict__ p,
                                        float* __restrict__ outp,
                                        int x0, int y0) {
    const bool lx = (x0 > 0);
    const bool rx = (x0 + 4 < 512);
    float* dst = outp + y0 * 512 + x0;

    float ra[6], rb[6], rc[6];              // rolling row registers
    float mn[6], mx[6];
    float lo[6], mi[6], hi[6];

    load_row<CHECK>(ra, p, y0 - 1, x0, lx, rx);   // r0
    load_row<CHECK>(rb, p, y0 + 0, x0, lx, rx);   // r1
    load_row<CHECK>(rc, p, y0 + 1, x0, lx, rx);   // r2

    // pair(r1, r2): serves windows A (r0-2) and B (r1-3); r1 dies, r2 kept for C.
    #pragma unroll
    for (int j = 0; j < 6; ++j) {
        mn[j] = fminf(rb[j], rc[j]);
        mx[j] = fmaxf(rb[j], rc[j]);
    }

    triples(ra, mn, mx, lo, mi, hi);              // window A; r0 dies
    load_row<CHECK>(ra, p, y0 + 2, x0, lx, rx);   // prefetch r3 into freed slot
    merge_row(lo, mi, hi, dst);

    triples(ra, mn, mx, lo, mi, hi);              // window B; mn/mx die after
    load_row<CHECK>(rb, p, y0 + 3, x0, lx, rx);   // prefetch r4
    merge_row(lo, mi, hi, dst + 512);

    // pair(r3, r4): serves windows C (r2-4) and D (r3-5); r3,r4 die.
    #pragma unroll
    for (int j = 0; j < 6; ++j) {
        mn[j] = fminf(ra[j], rb[j]);
        mx[j] = fmaxf(ra[j], rb[j]);
    }

    triples(rc, mn, mx, lo, mi, hi);              // window C; r2 dies
    load_row<CHECK>(rc, p, y0 + 4, x0, lx, rx);   // prefetch r5
    merge_row(lo, mi, hi, dst + 2 * 512);

    triples(rc, mn, mx, lo, mi, hi);              // window D
    merge_row(lo, mi, hi, dst + 3 * 512);
}

__global__ __launch_bounds__(128, 10)
void MedianBlur_34505767256654_kernel(const float* __restrict__ in,
                                      float* __restrict__ out) {
    const int x0 = (blockIdx.x * 32 + threadIdx.x) * 4;   // 4 cols per thread
    const int y0 = (blockIdx.y * 4 + threadIdx.y) * 4;    // 4 rows per thread
    const int base = blockIdx.z * (512 * 512);            // 24 planes

    const float* __restrict__ p = in + base;
    float* __restrict__ o = out + base;

    // Only the top and bottom y-blocks touch the vertical border.
    if (blockIdx.y != 0 && blockIdx.y != 31) {
        tile4x4<false>(p, o, x0, y0);
    } else {
        tile4x4<true>(p, o, x0, y0);
    }
}

extern "C" void kernel_launch(void* const* d_in, const int* in_sizes, int n_in,
                              void* d_out, int out_size) {
    (void)in_sizes; (void)n_in; (void)out_size;
    const float* x = (const float*)d_in[0];
    float* out = (float*)d_out;

    dim3 block(32, 4, 1);                    // 128 threads, tile 128x16 per block
    dim3 grid(512 / 128, 512 / 16, 24);      // (4, 32, 24) = 3072 blocks
    MedianBlur_34505767256654_kernel<<<grid, block>>>(x, out);
}

// round 13
// speedup vs baseline: 1.1231x; 1.1231x over previous
#include <cuda_runtime.h>

// 3x3 median blur, zero padding, fp32 NCHW (8,3,512,512).
// R7 body (best measured): 2 rows x 4 cols per thread, shared vertical
// pair-sort, two-phase A/B merge. This round changes ONLY the launch shape:
// __launch_bounds__(128,14) -> 36-reg target -> 1792 thr/SM (87.5% occ) and
// 6144 blocks -> 2.97 waves (kills the 0.46-wave tail of the 6-blk config).
// Rationale: FMNMX is alu-pipe-only (0.5 IPC/SMSP) => issue ceiling ~62%;
// occupancy is the only lever that has moved alu utilization toward it.

__device__ __forceinline__ float med3(float a, float b, float c) {
    return fmaxf(fminf(a, b), fminf(fmaxf(a, b), c));
}
__device__ __forceinline__ float max3(float a, float b, float c) {
    return fmaxf(fmaxf(a, b), c);
}
__device__ __forceinline__ float min3(float a, float b, float c) {
    return fminf(fminf(a, b), c);
}

template <bool CHECK_Y>
__device__ __forceinline__ void tile2x4(const float* __restrict__ p,
                                        float* __restrict__ outp,
                                        int x0, int y0) {
    // Input window: rows y0-1 .. y0+2, cols x0-1 .. x0+4 (zero-padded).
    float v[4][6];
    const bool lx = (x0 > 0);
    const bool rx = (x0 + 4 < 512);

    #pragma unroll
    for (int i = 0; i < 4; ++i) {
        const int yy = y0 - 1 + i;
        if (CHECK_Y && (unsigned)yy >= 512u) {
            #pragma unroll
            for (int j = 0; j < 6; ++j) v[i][j] = 0.0f;
        } else {
            const float* __restrict__ row = p + yy * 512;
            const float4 a = *reinterpret_cast<const float4*>(row + x0);
            v[i][1] = a.x; v[i][2] = a.y; v[i][3] = a.z; v[i][4] = a.w;
            v[i][0] = lx ? row[x0 - 1] : 0.0f;
            v[i][5] = rx ? row[x0 + 4] : 0.0f;
        }
    }

    float* __restrict__ rowA = outp + y0 * 512 + x0;

    // ---- Phase 1: middle-pair sort + window A (rows 0-2), store row A ----
    float mn[6], mx[6];
    float alo[6], ami[6], ahi[6];
    #pragma unroll
    for (int j = 0; j < 6; ++j) {
        mn[j] = fminf(v[1][j], v[2][j]);
        mx[j] = fmaxf(v[1][j], v[2][j]);
        const float a = v[0][j];
        const float u = fmaxf(a, mn[j]);
        alo[j] = fminf(a, mn[j]);
        ami[j] = fminf(u, mx[j]);
        ahi[j] = fmaxf(u, mx[j]);
    }
    {
        float oA[4];
        #pragma unroll
        for (int k = 0; k < 4; ++k) {
            oA[k] = med3(max3(alo[k], alo[k + 1], alo[k + 2]),
                         med3(ami[k], ami[k + 1], ami[k + 2]),
                         min3(ahi[k], ahi[k + 1], ahi[k + 2]));
        }
        *reinterpret_cast<float4*>(rowA) = make_float4(oA[0], oA[1], oA[2], oA[3]);
    }

    // ---- Phase 2: window B (rows 1-3) from retained mn/mx + row 3 ----
    float blo[6], bmi[6], bhi[6];
    #pragma unroll
    for (int j = 0; j < 6; ++j) {
        const float d = v[3][j];
        const float w = fmaxf(d, mn[j]);
        blo[j] = fminf(d, mn[j]);
        bmi[j] = fminf(w, mx[j]);
        bhi[j] = fmaxf(w, mx[j]);
    }
    {
        float oB[4];
        #pragma unroll
        for (int k = 0; k < 4; ++k) {
            oB[k] = med3(max3(blo[k], blo[k + 1], blo[k + 2]),
                         med3(bmi[k], bmi[k + 1], bmi[k + 2]),
                         min3(bhi[k], bhi[k + 1], bhi[k + 2]));
        }
        *reinterpret_cast<float4*>(rowA + 512) = make_float4(oB[0], oB[1], oB[2], oB[3]);
    }
}

__global__ __launch_bounds__(128, 14)
void MedianBlur_34505767256654_kernel(const float* __restrict__ in,
                                      float* __restrict__ out) {
    const int x0 = (blockIdx.x * 32 + threadIdx.x) * 4;   // 4 cols per thread
    const int y0 = (blockIdx.y * 4 + threadIdx.y) * 2;    // 2 rows per thread
    const int base = blockIdx.z * (512 * 512);            // 24 planes

    const float* __restrict__ p = in + base;
    float* __restrict__ o = out + base;

    // Only the top and bottom y-blocks touch the vertical border.
    if (blockIdx.y != 0 && blockIdx.y != 63) {
        tile2x4<false>(p, o, x0, y0);
    } else {
        tile2x4<true>(p, o, x0, y0);
    }
}

extern "C" void kernel_launch(void* const* d_in, const int* in_sizes, int n_in,
                              void* d_out, int out_size) {
    (void)in_sizes; (void)n_in; (void)out_size;
    const float* x = (const float*)d_in[0];
    float* out = (float*)d_out;

    dim3 block(32, 4, 1);                    // 128 threads, tile 128x8 per block
    dim3 grid(512 / 128, 512 / 8, 24);       // (4, 64, 24) = 6144 blocks
    MedianBlur_34505767256654_kernel<<<grid, block>>>(x, out);
}

// round 14
// speedup vs baseline: 1.3258x; 1.1805x over previous
#include <cuda_runtime.h>

// 3x3 median blur, zero padding, fp32 NCHW (8,3,512,512).
// Body = R9 (cheapest instruction stream: 4 rows x 4 cols per thread,
// shared pair-sorts vertically, shared-pair merges horizontally, 16 alu
// ops/px). Schedule = single-wave persistent: 1024 CTAs x 3 consecutive
// tiles each (1024/148 = 6.9 CTAs/SM, all resident at 64 regs) -> no wave
// transitions, no tail quantization; adjacent tiles share halo lines in L1.

__device__ __forceinline__ float med3(float a, float b, float c) {
    return fmaxf(fminf(a, b), fminf(fmaxf(a, b), c));
}

__device__ __forceinline__ void triples(const float r[6], const float mn[6],
                                        const float mx[6],
                                        float lo[6], float mi[6], float hi[6]) {
    #pragma unroll
    for (int j = 0; j < 6; ++j) {
        const float u = fmaxf(r[j], mn[j]);
        lo[j] = fminf(r[j], mn[j]);
        mi[j] = fminf(u, mx[j]);
        hi[j] = fmaxf(u, mx[j]);
    }
}

__device__ __forceinline__ void merge_row(const float lo[6], const float mi[6],
                                          const float hi[6], float* dst) {
    const float m12 = fmaxf(lo[1], lo[2]);
    const float m34 = fmaxf(lo[3], lo[4]);
    const float A0 = fmaxf(lo[0], m12);
    const float A1 = fmaxf(m12, lo[3]);
    const float A2 = fmaxf(lo[2], m34);
    const float A3 = fmaxf(m34, lo[5]);
    const float n12 = fminf(hi[1], hi[2]);
    const float n34 = fminf(hi[3], hi[4]);
    const float C0 = fminf(hi[0], n12);
    const float C1 = fminf(n12, hi[3]);
    const float C2 = fminf(hi[2], n34);
    const float C3 = fminf(n34, hi[5]);
    const float p12 = fminf(mi[1], mi[2]), q12 = fmaxf(mi[1], mi[2]);
    const float p34 = fminf(mi[3], mi[4]), q34 = fmaxf(mi[3], mi[4]);
    const float B0 = fmaxf(p12, fminf(mi[0], q12));
    const float B1 = fmaxf(p12, fminf(mi[3], q12));
    const float B2 = fmaxf(p34, fminf(mi[2], q34));
    const float B3 = fmaxf(p34, fminf(mi[5], q34));
    float4 o;
    o.x = med3(A0, B0, C0);
    o.y = med3(A1, B1, C1);
    o.z = med3(A2, B2, C2);
    o.w = med3(A3, B3, C3);
    *reinterpret_cast<float4*>(dst) = o;
}

template <bool CHECK_Y>
__device__ __forceinline__ void tile4x4(const float* __restrict__ p,
                                        float* __restrict__ outp,
                                        int x0, int y0) {
    // Input rows y0-1 .. y0+4, cols x0-1 .. x0+4 (zero-padded).
    float v[6][6];
    const bool lx = (x0 > 0);
    const bool rx = (x0 + 4 < 512);

    #pragma unroll
    for (int i = 0; i < 6; ++i) {
        const int yy = y0 - 1 + i;
        if (CHECK_Y && (unsigned)yy >= 512u) {
            #pragma unroll
            for (int j = 0; j < 6; ++j) v[i][j] = 0.0f;
        } else {
            const float* __restrict__ row = p + yy * 512;
            const float4 a = *reinterpret_cast<const float4*>(row + x0);
            v[i][1] = a.x; v[i][2] = a.y; v[i][3] = a.z; v[i][4] = a.w;
            v[i][0] = lx ? row[x0 - 1] : 0.0f;
            v[i][5] = rx ? row[x0 + 4] : 0.0f;
        }
    }

    float* __restrict__ orow = outp + y0 * 512 + x0;
    float t_lo[6], t_mi[6], t_hi[6];
    float mn[6], mx[6];

    // Pair (r1, r2) serves windows A (r0-2) and B (r1-3).
    #pragma unroll
    for (int j = 0; j < 6; ++j) {
        mn[j] = fminf(v[1][j], v[2][j]);
        mx[j] = fmaxf(v[1][j], v[2][j]);
    }
    triples(v[0], mn, mx, t_lo, t_mi, t_hi);
    merge_row(t_lo, t_mi, t_hi, orow);
    triples(v[3], mn, mx, t_lo, t_mi, t_hi);
    merge_row(t_lo, t_mi, t_hi, orow + 512);

    // Pair (r3, r4) serves windows C (r2-4) and D (r3-5).
    #pragma unroll
    for (int j = 0; j < 6; ++j) {
        mn[j] = fminf(v[3][j], v[4][j]);
        mx[j] = fmaxf(v[3][j], v[4][j]);
    }
    triples(v[2], mn, mx, t_lo, t_mi, t_hi);
    merge_row(t_lo, t_mi, t_hi, orow + 2 * 512);
    triples(v[5], mn, mx, t_lo, t_mi, t_hi);
    merge_row(t_lo, t_mi, t_hi, orow + 3 * 512);
}

__global__ __launch_bounds__(128, 8)
void MedianBlur_34505767256654_kernel(const float* __restrict__ in,
                                      float* __restrict__ out) {
    // Persistent single-wave mapping: 1024 CTAs x 3 consecutive tiles.
    // Tile index t in [0, 3072): t = ((z * 32) + yb) * 4 + xb
    //   xb in [0,4): 128-px x-slab;  yb in [0,32): 16-row y-slab;  z: plane.
    const int t0 = blockIdx.x * 3;

    #pragma unroll 1
    for (int i = 0; i < 3; ++i) {
        const int t = t0 + i;
        const int xb = t & 3;
        const int yb = (t >> 2) & 31;
        const int z  = t >> 7;

        const int x0 = xb * 128 + threadIdx.x * 4;        // 4 cols per thread
        const int y0 = yb * 16 + threadIdx.y * 4;         // 4 rows per thread
        const int base = z * (512 * 512);

        const float* __restrict__ p = in + base;
        float* __restrict__ o = out + base;

        if (yb != 0 && yb != 31) {
            tile4x4<false>(p, o, x0, y0);
        } else {
            tile4x4<true>(p, o, x0, y0);
        }
    }
}

extern "C" void kernel_launch(void* const* d_in, const int* in_sizes, int n_in,
                              void* d_out, int out_size) {
    (void)in_sizes; (void)n_in; (void)out_size;
    const float* x = (const float*)d_in[0];
    float* out = (float*)d_out;

    dim3 block(32, 4, 1);                 // 128 threads, tile 128x16
    dim3 grid(1024, 1, 1);                // 1024 CTAs x 3 tiles = 3072 tiles
    MedianBlur_34505767256654_kernel<<<grid, block>>>(x, out);
}